// round 1
// baseline (speedup 1.0000x reference)
#include <cuda_runtime.h>
#include <cuda_bf16.h>
#include <math.h>

#define N_NODES 50000
#define N_EDGES 800000
#define IN_DIM  512
#define HIDDEN  128
#define OUT_DIM 64
#define EPS_F   0.3f

// ---------------- scratch (device globals; no allocation allowed) -----------
__device__ float g_h0[N_NODES * HIDDEN];   // raw (after transform1)
__device__ float g_hA[N_NODES * HIDDEN];   // h after layer 0
__device__ float g_hB[N_NODES * HIDDEN];   // h after layer 1
__device__ float g_sdst[N_NODES];
__device__ float g_ssrc[N_NODES];
__device__ float g_ecoef[N_EDGES];
__device__ int   g_counts[N_NODES];
__device__ int   g_rowptr[N_NODES + 1];
__device__ int   g_cursor[N_NODES];
__device__ int   g_perm[N_EDGES];

__device__ __forceinline__ const float* hbuf(int w) {
    return w == 0 ? g_h0 : (w == 1 ? g_hA : g_hB);
}
__device__ __forceinline__ float* hbuf_mut(int w) {
    return w == 0 ? g_h0 : (w == 1 ? g_hA : g_hB);
}

// ---------------- GEMM1 + ReLU:  g_h0 = relu(A[M,512] @ W[128,512]^T + b) ---
__global__ void gemm1_relu_kernel(const float* __restrict__ A,
                                  const float* __restrict__ W,
                                  const float* __restrict__ bias) {
    __shared__ float Ast[8 * 128];  // [k][row]
    __shared__ float Ws [8 * 128];  // [k][col]
    const int tid = threadIdx.x;
    const int tx = tid & 15, ty = tid >> 4;       // 16x16 thread tile
    const int block_row = blockIdx.x * 128;
    const int half  = tid & 1;
    const int ldrow = tid >> 1;                   // 0..127

    float acc[8][8];
#pragma unroll
    for (int i = 0; i < 8; i++)
#pragma unroll
        for (int j = 0; j < 8; j++) acc[i][j] = 0.f;

    for (int k0 = 0; k0 < IN_DIM; k0 += 8) {
        // A tile: rows block_row..+127, k k0..k0+7  -> Ast[k][row]
        float4 av = make_float4(0.f, 0.f, 0.f, 0.f);
        int grow = block_row + ldrow;
        if (grow < N_NODES)
            av = *(const float4*)&A[grow * IN_DIM + k0 + half * 4];
        Ast[(half * 4 + 0) * 128 + ldrow] = av.x;
        Ast[(half * 4 + 1) * 128 + ldrow] = av.y;
        Ast[(half * 4 + 2) * 128 + ldrow] = av.z;
        Ast[(half * 4 + 3) * 128 + ldrow] = av.w;
        // W tile: W[col][k] -> Ws[k][col]
        float4 wv = *(const float4*)&W[ldrow * IN_DIM + k0 + half * 4];
        Ws[(half * 4 + 0) * 128 + ldrow] = wv.x;
        Ws[(half * 4 + 1) * 128 + ldrow] = wv.y;
        Ws[(half * 4 + 2) * 128 + ldrow] = wv.z;
        Ws[(half * 4 + 3) * 128 + ldrow] = wv.w;
        __syncthreads();
#pragma unroll
        for (int k = 0; k < 8; k++) {
            float4 a0 = *(const float4*)&Ast[k * 128 + ty * 8];
            float4 a1 = *(const float4*)&Ast[k * 128 + ty * 8 + 4];
            float4 b0 = *(const float4*)&Ws [k * 128 + tx * 8];
            float4 b1 = *(const float4*)&Ws [k * 128 + tx * 8 + 4];
            float ar[8] = {a0.x, a0.y, a0.z, a0.w, a1.x, a1.y, a1.z, a1.w};
            float br[8] = {b0.x, b0.y, b0.z, b0.w, b1.x, b1.y, b1.z, b1.w};
#pragma unroll
            for (int i = 0; i < 8; i++)
#pragma unroll
                for (int j = 0; j < 8; j++) acc[i][j] = fmaf(ar[i], br[j], acc[i][j]);
        }
        __syncthreads();
    }
#pragma unroll
    for (int i = 0; i < 8; i++) {
        int grow = block_row + ty * 8 + i;
        if (grow < N_NODES) {
#pragma unroll
            for (int j = 0; j < 8; j++) {
                int col = tx * 8 + j;
                float v = acc[i][j] + bias[col];
                g_h0[grow * HIDDEN + col] = fmaxf(v, 0.f);
            }
        }
    }
}

// ---------------- CSR build ------------------------------------------------
__global__ void zero_counts_kernel() {
    int i = blockIdx.x * blockDim.x + threadIdx.x;
    if (i < N_NODES) g_counts[i] = 0;
}
__global__ void hist_kernel(const int* __restrict__ dst) {
    int i = blockIdx.x * blockDim.x + threadIdx.x;
    if (i < N_EDGES) atomicAdd(&g_counts[dst[i]], 1);
}
__global__ void scan_kernel() {
    __shared__ int sm[1024];
    __shared__ int carry;
    const int t = threadIdx.x;
    if (t == 0) carry = 0;
    __syncthreads();
    for (int base = 0; base < N_NODES; base += 1024) {
        int i = base + t;
        int v = (i < N_NODES) ? g_counts[i] : 0;
        sm[t] = v;
        __syncthreads();
        for (int off = 1; off < 1024; off <<= 1) {
            int x = 0;
            if (t >= off) x = sm[t - off];
            __syncthreads();
            sm[t] += x;
            __syncthreads();
        }
        int incl = sm[t];
        int chunk_total = sm[1023];
        int ex = carry + incl - v;
        if (i < N_NODES) { g_rowptr[i] = ex; g_cursor[i] = ex; }
        __syncthreads();
        if (t == 0) carry += chunk_total;
        __syncthreads();
    }
    if (t == 0) g_rowptr[N_NODES] = N_EDGES;
}
__global__ void scatter_kernel(const int* __restrict__ dst) {
    int i = blockIdx.x * blockDim.x + threadIdx.x;
    if (i < N_EDGES) {
        int pos = atomicAdd(&g_cursor[dst[i]], 1);
        g_perm[pos] = i;
    }
}

// ---------------- gate scalar projections ----------------------------------
// s_dst[n] = dot(h[n], gate_w[layer, :128]); s_src[n] = dot(h[n], gate_w[layer,128:])
__global__ void gate_proj_kernel(int hin_sel, const float* __restrict__ gate_w,
                                 int layer) {
    int warp = (blockIdx.x * blockDim.x + threadIdx.x) >> 5;
    int lane = threadIdx.x & 31;
    if (warp >= N_NODES) return;
    const float* __restrict__ h = hbuf(hin_sel);
    const float* wd = gate_w + layer * (2 * HIDDEN);
    const float* ws = wd + HIDDEN;
    const float* hr = h + (size_t)warp * HIDDEN;
    float a0 = 0.f, a1 = 0.f;
#pragma unroll
    for (int j = lane; j < HIDDEN; j += 32) {
        float hv = hr[j];
        a0 = fmaf(hv, wd[j], a0);
        a1 = fmaf(hv, ws[j], a1);
    }
#pragma unroll
    for (int off = 16; off; off >>= 1) {
        a0 += __shfl_xor_sync(0xffffffffu, a0, off);
        a1 += __shfl_xor_sync(0xffffffffu, a1, off);
    }
    if (lane == 0) { g_sdst[warp] = a0; g_ssrc[warp] = a1; }
}

// ---------------- per-edge coefficients ------------------------------------
__global__ void edge_coef_kernel(const int* __restrict__ src,
                                 const int* __restrict__ dst,
                                 const float* __restrict__ d,
                                 const float* __restrict__ gate_b, int layer) {
    int i = blockIdx.x * blockDim.x + threadIdx.x;
    if (i >= N_EDGES) return;
    int s = src[i], t = dst[i];
    float g = tanhf(g_sdst[t] + g_ssrc[s] + gate_b[layer]);
    g_ecoef[i] = g * d[t] * d[s];
}

// ---------------- aggregation: h_out = EPS*raw + segment_sum ---------------
__global__ void agg_kernel(int hin_sel, int hout_sel,
                           const int* __restrict__ src) {
    int warp = (blockIdx.x * blockDim.x + threadIdx.x) >> 5;
    int lane = threadIdx.x & 31;
    if (warp >= N_NODES) return;
    const float* __restrict__ h_in = hbuf(hin_sel);
    float* __restrict__ h_out = hbuf_mut(hout_sel);
    int rs = g_rowptr[warp], re = g_rowptr[warp + 1];
    float4 acc = make_float4(0.f, 0.f, 0.f, 0.f);
    for (int p = rs; p < re; ++p) {
        int e = __ldg(&g_perm[p]);
        int s = __ldg(&src[e]);
        float ev = __ldg(&g_ecoef[e]);
        float4 hv = *(const float4*)&h_in[(size_t)s * HIDDEN + lane * 4];
        acc.x = fmaf(ev, hv.x, acc.x);
        acc.y = fmaf(ev, hv.y, acc.y);
        acc.z = fmaf(ev, hv.z, acc.z);
        acc.w = fmaf(ev, hv.w, acc.w);
    }
    float4 rv = *(const float4*)&g_h0[(size_t)warp * HIDDEN + lane * 4];
    float4 o;
    o.x = fmaf(EPS_F, rv.x, acc.x);
    o.y = fmaf(EPS_F, rv.y, acc.y);
    o.z = fmaf(EPS_F, rv.z, acc.z);
    o.w = fmaf(EPS_F, rv.w, acc.w);
    *(float4*)&h_out[(size_t)warp * HIDDEN + lane * 4] = o;
}

// ---------------- final: out = log_softmax(h @ t2_w^T + t2_b) --------------
__global__ void out_kernel(int hin_sel, const float* __restrict__ W2,
                           const float* __restrict__ b2,
                           float* __restrict__ out) {
    __shared__ float wt[HIDDEN * OUT_DIM];  // wt[k*64 + j] = W2[j*128 + k]
    __shared__ float b2s[OUT_DIM];
    __shared__ float hrow[8][HIDDEN];
    for (int idx = threadIdx.x; idx < OUT_DIM * HIDDEN; idx += blockDim.x) {
        int j = idx >> 7;        // out col
        int k = idx & 127;       // hidden idx
        wt[k * OUT_DIM + j] = W2[idx];
    }
    if (threadIdx.x < OUT_DIM) b2s[threadIdx.x] = b2[threadIdx.x];
    __syncthreads();

    const float* __restrict__ h = hbuf(hin_sel);
    const int lane = threadIdx.x & 31;
    const int wlocal = threadIdx.x >> 5;
    const int nwarps = (gridDim.x * blockDim.x) >> 5;
    for (int n = (blockIdx.x * blockDim.x + threadIdx.x) >> 5; n < N_NODES;
         n += nwarps) {
        float4 hv = *(const float4*)&h[(size_t)n * HIDDEN + lane * 4];
        *(float4*)&hrow[wlocal][lane * 4] = hv;
        __syncwarp();
        float acc0 = b2s[lane], acc1 = b2s[lane + 32];
#pragma unroll 8
        for (int k = 0; k < HIDDEN; k++) {
            float hk = hrow[wlocal][k];
            acc0 = fmaf(hk, wt[k * OUT_DIM + lane], acc0);
            acc1 = fmaf(hk, wt[k * OUT_DIM + lane + 32], acc1);
        }
        float m = fmaxf(acc0, acc1);
#pragma unroll
        for (int off = 16; off; off >>= 1)
            m = fmaxf(m, __shfl_xor_sync(0xffffffffu, m, off));
        float s = expf(acc0 - m) + expf(acc1 - m);
#pragma unroll
        for (int off = 16; off; off >>= 1)
            s += __shfl_xor_sync(0xffffffffu, s, off);
        float lse = m + logf(s);
        out[(size_t)n * OUT_DIM + lane]      = acc0 - lse;
        out[(size_t)n * OUT_DIM + lane + 32] = acc1 - lse;
        __syncwarp();
    }
}

// ---------------- launch ----------------------------------------------------
extern "C" void kernel_launch(void* const* d_in, const int* in_sizes, int n_in,
                              void* d_out, int out_size) {
    const float* h      = (const float*)d_in[0];
    const int*   src    = (const int*)d_in[1];
    const int*   dst    = (const int*)d_in[2];
    const float* d      = (const float*)d_in[3];
    const float* t1_w   = (const float*)d_in[4];
    const float* t1_b   = (const float*)d_in[5];
    const float* gate_w = (const float*)d_in[6];
    const float* gate_b = (const float*)d_in[7];
    const float* t2_w   = (const float*)d_in[8];
    const float* t2_b   = (const float*)d_in[9];
    float* out = (float*)d_out;

    // transform 1
    gemm1_relu_kernel<<<(N_NODES + 127) / 128, 256>>>(h, t1_w, t1_b);

    // CSR by dst (fixed across layers)
    zero_counts_kernel<<<(N_NODES + 255) / 256, 256>>>();
    hist_kernel<<<(N_EDGES + 255) / 256, 256>>>(dst);
    scan_kernel<<<1, 1024>>>();
    scatter_kernel<<<(N_EDGES + 255) / 256, 256>>>(dst);

    const int node_warp_blocks = (N_NODES * 32 + 255) / 256;  // 6250
    const int edge_blocks = (N_EDGES + 255) / 256;

    // layer 0: h_cur = g_h0 (sel 0) -> g_hA (sel 1)
    gate_proj_kernel<<<node_warp_blocks, 256>>>(0, gate_w, 0);
    edge_coef_kernel<<<edge_blocks, 256>>>(src, dst, d, gate_b, 0);
    agg_kernel<<<node_warp_blocks, 256>>>(0, 1, src);

    // layer 1: g_hA -> g_hB (sel 2)
    gate_proj_kernel<<<node_warp_blocks, 256>>>(1, gate_w, 1);
    edge_coef_kernel<<<edge_blocks, 256>>>(src, dst, d, gate_b, 1);
    agg_kernel<<<node_warp_blocks, 256>>>(1, 2, src);

    // output head + log_softmax
    out_kernel<<<592, 256>>>(2, t2_w, t2_b, out);
}

// round 2
// speedup vs baseline: 1.5784x; 1.5784x over previous
#include <cuda_runtime.h>
#include <cuda_bf16.h>
#include <math.h>
#include <stdint.h>

#define N_NODES 50000
#define N_EDGES 800000
#define IN_DIM  512
#define HIDDEN  128
#define OUT_DIM 64
#define EPS_F   0.3f
#define SCAN_NB 49           // ceil(50000/1024)

// ---------------- scratch (device globals; no allocation allowed) -----------
__device__ float g_h0[N_NODES * HIDDEN];   // raw (after transform1)
__device__ float g_hA[N_NODES * HIDDEN];   // h after layer 0
__device__ float g_hB[N_NODES * HIDDEN];   // h after layer 1
__device__ float g_sdst[N_NODES];
__device__ float g_ssrc[N_NODES];
__device__ float g_ecoef[N_EDGES];
__device__ int   g_counts[N_NODES];
__device__ int   g_rowptr[N_NODES + 1];
__device__ int   g_cursor[N_NODES];
__device__ int   g_perm[N_EDGES];
__device__ int   g_blocksums[64];
__device__ __nv_bfloat16 g_w_hi[HIDDEN * IN_DIM];
__device__ __nv_bfloat16 g_w_lo[HIDDEN * IN_DIM];

__device__ __forceinline__ const float* hbuf(int w) {
    return w == 0 ? g_h0 : (w == 1 ? g_hA : g_hB);
}
__device__ __forceinline__ float* hbuf_mut(int w) {
    return w == 0 ? g_h0 : (w == 1 ? g_hA : g_hB);
}

// ---------------- W split-precision conversion ------------------------------
__global__ void wconv_kernel(const float* __restrict__ W) {
    int i = blockIdx.x * blockDim.x + threadIdx.x;
    if (i < HIDDEN * IN_DIM) {
        float v = W[i];
        __nv_bfloat16 h = __float2bfloat16_rn(v);
        g_w_hi[i] = h;
        g_w_lo[i] = __float2bfloat16_rn(v - __bfloat162float(h));
    }
}

// ---------------- GEMM1 via split-bf16 tensor cores --------------------------
// g_h0 = relu(A[50000,512] @ W[128,512]^T + b), fp32-accurate via hi/lo bf16.
#define GP 20  // smem row pitch in 32-bit words (= 40 bf16); conflict-free frag loads

__device__ __forceinline__ uint32_t pack2(__nv_bfloat16 a, __nv_bfloat16 b) {
    uint16_t ua = *reinterpret_cast<uint16_t*>(&a);
    uint16_t ub = *reinterpret_cast<uint16_t*>(&b);
    return (uint32_t)ua | ((uint32_t)ub << 16);
}

__device__ __forceinline__ void mma_bf16(float* d, const uint32_t* a,
                                         uint32_t b0, uint32_t b1) {
    asm volatile(
        "mma.sync.aligned.m16n8k16.row.col.f32.bf16.bf16.f32 "
        "{%0,%1,%2,%3},{%4,%5,%6,%7},{%8,%9},{%0,%1,%2,%3};\n"
        : "+f"(d[0]), "+f"(d[1]), "+f"(d[2]), "+f"(d[3])
        : "r"(a[0]), "r"(a[1]), "r"(a[2]), "r"(a[3]), "r"(b0), "r"(b1));
}

__global__ void __launch_bounds__(256)
gemm1_mma_kernel(const float* __restrict__ A, const float* __restrict__ bias) {
    __shared__ uint32_t asH[128 * GP], asL[128 * GP];
    __shared__ uint32_t bsH[128 * GP], bsL[128 * GP];
    const int tid = threadIdx.x;
    const int brow = blockIdx.x * 128;
    const int warp = tid >> 5, lane = tid & 31;
    const int wm = warp >> 1, wn = warp & 1;
    const int ldrow = tid >> 1, half = tid & 1;

    float acc[2][8][4];
#pragma unroll
    for (int mt = 0; mt < 2; mt++)
#pragma unroll
        for (int nt = 0; nt < 8; nt++)
#pragma unroll
            for (int q = 0; q < 4; q++) acc[mt][nt][q] = 0.f;

    const int arow = min(brow + ldrow, N_NODES - 1);
    const float4* __restrict__ ag =
        (const float4*)&A[(size_t)arow * IN_DIM + half * 16];
    const uint4* __restrict__ bgh =
        (const uint4*)&g_w_hi[ldrow * IN_DIM + half * 16];
    const uint4* __restrict__ bgl =
        (const uint4*)&g_w_lo[ldrow * IN_DIM + half * 16];

    for (int k0 = 0; k0 < IN_DIM; k0 += 32) {
        // --- stage A (fp32 -> hi/lo bf16) ---
#pragma unroll
        for (int q = 0; q < 4; q++) {
            float4 v = ag[(k0 >> 2) + q];
            __nv_bfloat16 hx = __float2bfloat16_rn(v.x);
            __nv_bfloat16 hy = __float2bfloat16_rn(v.y);
            __nv_bfloat16 hz = __float2bfloat16_rn(v.z);
            __nv_bfloat16 hw = __float2bfloat16_rn(v.w);
            __nv_bfloat16 lx = __float2bfloat16_rn(v.x - __bfloat162float(hx));
            __nv_bfloat16 ly = __float2bfloat16_rn(v.y - __bfloat162float(hy));
            __nv_bfloat16 lz = __float2bfloat16_rn(v.z - __bfloat162float(hz));
            __nv_bfloat16 lw = __float2bfloat16_rn(v.w - __bfloat162float(hw));
            int w = half * 8 + q * 2;
            *(uint2*)&asH[ldrow * GP + w] = make_uint2(pack2(hx, hy), pack2(hz, hw));
            *(uint2*)&asL[ldrow * GP + w] = make_uint2(pack2(lx, ly), pack2(lz, lw));
        }
        // --- stage B (preconverted bf16 hi/lo) ---
#pragma unroll
        for (int q = 0; q < 2; q++) {
            uint4 bh = bgh[(k0 >> 3) + q];
            uint4 bl = bgl[(k0 >> 3) + q];
            *(uint4*)&bsH[ldrow * GP + half * 8 + q * 4] = bh;
            *(uint4*)&bsL[ldrow * GP + half * 8 + q * 4] = bl;
        }
        __syncthreads();
        // --- compute: 2 k16 steps ---
#pragma unroll
        for (int kk = 0; kk < 2; kk++) {
            const int kw = kk * 8 + (lane & 3);
            uint32_t aH[2][4], aL[2][4];
#pragma unroll
            for (int mt = 0; mt < 2; mt++) {
                int r = wm * 32 + mt * 16 + (lane >> 2);
                aH[mt][0] = asH[r * GP + kw];
                aH[mt][1] = asH[(r + 8) * GP + kw];
                aH[mt][2] = asH[r * GP + kw + 4];
                aH[mt][3] = asH[(r + 8) * GP + kw + 4];
                aL[mt][0] = asL[r * GP + kw];
                aL[mt][1] = asL[(r + 8) * GP + kw];
                aL[mt][2] = asL[r * GP + kw + 4];
                aL[mt][3] = asL[(r + 8) * GP + kw + 4];
            }
#pragma unroll
            for (int nt = 0; nt < 8; nt++) {
                int n = wn * 64 + nt * 8 + (lane >> 2);
                uint32_t bH0 = bsH[n * GP + kw], bH1 = bsH[n * GP + kw + 4];
                uint32_t bL0 = bsL[n * GP + kw], bL1 = bsL[n * GP + kw + 4];
#pragma unroll
                for (int mt = 0; mt < 2; mt++) {
                    mma_bf16(acc[mt][nt], aH[mt], bH0, bH1);
                    mma_bf16(acc[mt][nt], aL[mt], bH0, bH1);
                    mma_bf16(acc[mt][nt], aH[mt], bL0, bL1);
                }
            }
        }
        __syncthreads();
    }
    // --- epilogue: bias + relu ---
#pragma unroll
    for (int mt = 0; mt < 2; mt++) {
        int r0 = brow + wm * 32 + mt * 16 + (lane >> 2);
#pragma unroll
        for (int nt = 0; nt < 8; nt++) {
            int c = wn * 64 + nt * 8 + (lane & 3) * 2;
            float b0 = __ldg(&bias[c]), b1 = __ldg(&bias[c + 1]);
            if (r0 < N_NODES) {
                g_h0[(size_t)r0 * HIDDEN + c]     = fmaxf(acc[mt][nt][0] + b0, 0.f);
                g_h0[(size_t)r0 * HIDDEN + c + 1] = fmaxf(acc[mt][nt][1] + b1, 0.f);
            }
            if (r0 + 8 < N_NODES) {
                g_h0[(size_t)(r0 + 8) * HIDDEN + c]     = fmaxf(acc[mt][nt][2] + b0, 0.f);
                g_h0[(size_t)(r0 + 8) * HIDDEN + c + 1] = fmaxf(acc[mt][nt][3] + b1, 0.f);
            }
        }
    }
}

// ---------------- CSR build -------------------------------------------------
__global__ void zero_counts_kernel() {
    int i = blockIdx.x * blockDim.x + threadIdx.x;
    if (i < N_NODES) g_counts[i] = 0;
}
__global__ void hist_kernel(const int* __restrict__ dst) {
    int i = blockIdx.x * blockDim.x + threadIdx.x;
    if (i < N_EDGES) atomicAdd(&g_counts[dst[i]], 1);
}
// level 1: per-1024-block exclusive scan, block sums out
__global__ void scan_blocks_kernel() {
    __shared__ int wsum[32];
    const int t = threadIdx.x, lane = t & 31, wid = t >> 5;
    const int i = blockIdx.x * 1024 + t;
    int v = (i < N_NODES) ? g_counts[i] : 0;
    int x = v;
#pragma unroll
    for (int off = 1; off < 32; off <<= 1) {
        int y = __shfl_up_sync(0xffffffffu, x, off);
        if (lane >= off) x += y;
    }
    if (lane == 31) wsum[wid] = x;
    __syncthreads();
    if (wid == 0) {
        int s = wsum[lane];
#pragma unroll
        for (int off = 1; off < 32; off <<= 1) {
            int y = __shfl_up_sync(0xffffffffu, s, off);
            if (lane >= off) s += y;
        }
        wsum[lane] = s;
    }
    __syncthreads();
    int incl = x + (wid > 0 ? wsum[wid - 1] : 0);
    if (i < N_NODES) g_rowptr[i] = incl - v;  // local exclusive
    if (t == 1023) g_blocksums[blockIdx.x] = incl;
}
// level 2: exclusive scan of 49 block sums
__global__ void scan_sums_kernel() {
    __shared__ int sm[64];
    int t = threadIdx.x;
    int v = (t < SCAN_NB) ? g_blocksums[t] : 0;
    sm[t] = v;
    __syncthreads();
    for (int off = 1; off < 64; off <<= 1) {
        int x = (t >= off) ? sm[t - off] : 0;
        __syncthreads();
        sm[t] += x;
        __syncthreads();
    }
    if (t < SCAN_NB) g_blocksums[t] = sm[t] - v;
}
// level 3: add block offsets, fill cursor
__global__ void add_offsets_kernel() {
    int i = blockIdx.x * blockDim.x + threadIdx.x;
    if (i < N_NODES) {
        int r = g_rowptr[i] + g_blocksums[i >> 10];
        g_rowptr[i] = r;
        g_cursor[i] = r;
    }
    if (i == 0) g_rowptr[N_NODES] = N_EDGES;
}
__global__ void scatter_kernel(const int* __restrict__ dst) {
    int i = blockIdx.x * blockDim.x + threadIdx.x;
    if (i < N_EDGES) {
        int pos = atomicAdd(&g_cursor[dst[i]], 1);
        g_perm[pos] = i;
    }
}

// ---------------- gate scalar projections -----------------------------------
__global__ void gate_proj_kernel(int hin_sel, const float* __restrict__ gate_w,
                                 int layer) {
    int warp = (blockIdx.x * blockDim.x + threadIdx.x) >> 5;
    int lane = threadIdx.x & 31;
    if (warp >= N_NODES) return;
    const float* __restrict__ h = hbuf(hin_sel);
    const float* wd = gate_w + layer * (2 * HIDDEN);
    const float* ws = wd + HIDDEN;
    const float* hr = h + (size_t)warp * HIDDEN;
    float a0 = 0.f, a1 = 0.f;
#pragma unroll
    for (int j = lane; j < HIDDEN; j += 32) {
        float hv = hr[j];
        a0 = fmaf(hv, wd[j], a0);
        a1 = fmaf(hv, ws[j], a1);
    }
#pragma unroll
    for (int off = 16; off; off >>= 1) {
        a0 += __shfl_xor_sync(0xffffffffu, a0, off);
        a1 += __shfl_xor_sync(0xffffffffu, a1, off);
    }
    if (lane == 0) { g_sdst[warp] = a0; g_ssrc[warp] = a1; }
}

// ---------------- per-edge coefficients -------------------------------------
__global__ void edge_coef_kernel(const int* __restrict__ src,
                                 const int* __restrict__ dst,
                                 const float* __restrict__ d,
                                 const float* __restrict__ gate_b, int layer) {
    int i = blockIdx.x * blockDim.x + threadIdx.x;
    if (i >= N_EDGES) return;
    int s = src[i], t = dst[i];
    float g = tanhf(g_sdst[t] + g_ssrc[s] + gate_b[layer]);
    g_ecoef[i] = g * d[t] * d[s];
}

// ---------------- aggregation: h_out = EPS*raw + segment_sum ----------------
__global__ void agg_kernel(int hin_sel, int hout_sel,
                           const int* __restrict__ src) {
    int warp = (blockIdx.x * blockDim.x + threadIdx.x) >> 5;
    int lane = threadIdx.x & 31;
    if (warp >= N_NODES) return;
    const float* __restrict__ h_in = hbuf(hin_sel);
    float* __restrict__ h_out = hbuf_mut(hout_sel);
    int rs = g_rowptr[warp], re = g_rowptr[warp + 1];
    float4 acc = make_float4(0.f, 0.f, 0.f, 0.f);
    for (int p = rs; p < re; ++p) {
        int e = __ldg(&g_perm[p]);
        int s = __ldg(&src[e]);
        float ev = __ldg(&g_ecoef[e]);
        float4 hv = *(const float4*)&h_in[(size_t)s * HIDDEN + lane * 4];
        acc.x = fmaf(ev, hv.x, acc.x);
        acc.y = fmaf(ev, hv.y, acc.y);
        acc.z = fmaf(ev, hv.z, acc.z);
        acc.w = fmaf(ev, hv.w, acc.w);
    }
    float4 rv = *(const float4*)&g_h0[(size_t)warp * HIDDEN + lane * 4];
    float4 o;
    o.x = fmaf(EPS_F, rv.x, acc.x);
    o.y = fmaf(EPS_F, rv.y, acc.y);
    o.z = fmaf(EPS_F, rv.z, acc.z);
    o.w = fmaf(EPS_F, rv.w, acc.w);
    *(float4*)&h_out[(size_t)warp * HIDDEN + lane * 4] = o;
}

// ---------------- final: out = log_softmax(h @ t2_w^T + t2_b) ---------------
__global__ void out_kernel(int hin_sel, const float* __restrict__ W2,
                           const float* __restrict__ b2,
                           float* __restrict__ out) {
    __shared__ float wt[HIDDEN * OUT_DIM];
    __shared__ float b2s[OUT_DIM];
    __shared__ float hrow[8][HIDDEN];
    for (int idx = threadIdx.x; idx < OUT_DIM * HIDDEN; idx += blockDim.x) {
        int j = idx >> 7;
        int k = idx & 127;
        wt[k * OUT_DIM + j] = W2[idx];
    }
    if (threadIdx.x < OUT_DIM) b2s[threadIdx.x] = b2[threadIdx.x];
    __syncthreads();

    const float* __restrict__ h = hbuf(hin_sel);
    const int lane = threadIdx.x & 31;
    const int wlocal = threadIdx.x >> 5;
    const int nwarps = (gridDim.x * blockDim.x) >> 5;
    for (int n = (blockIdx.x * blockDim.x + threadIdx.x) >> 5; n < N_NODES;
         n += nwarps) {
        float4 hv = *(const float4*)&h[(size_t)n * HIDDEN + lane * 4];
        *(float4*)&hrow[wlocal][lane * 4] = hv;
        __syncwarp();
        float acc0 = b2s[lane], acc1 = b2s[lane + 32];
#pragma unroll 8
        for (int k = 0; k < HIDDEN; k++) {
            float hk = hrow[wlocal][k];
            acc0 = fmaf(hk, wt[k * OUT_DIM + lane], acc0);
            acc1 = fmaf(hk, wt[k * OUT_DIM + lane + 32], acc1);
        }
        float m = fmaxf(acc0, acc1);
#pragma unroll
        for (int off = 16; off; off >>= 1)
            m = fmaxf(m, __shfl_xor_sync(0xffffffffu, m, off));
        float s = expf(acc0 - m) + expf(acc1 - m);
#pragma unroll
        for (int off = 16; off; off >>= 1)
            s += __shfl_xor_sync(0xffffffffu, s, off);
        float lse = m + logf(s);
        out[(size_t)n * OUT_DIM + lane]      = acc0 - lse;
        out[(size_t)n * OUT_DIM + lane + 32] = acc1 - lse;
        __syncwarp();
    }
}

// ---------------- launch ----------------------------------------------------
extern "C" void kernel_launch(void* const* d_in, const int* in_sizes, int n_in,
                              void* d_out, int out_size) {
    const float* h      = (const float*)d_in[0];
    const int*   src    = (const int*)d_in[1];
    const int*   dst    = (const int*)d_in[2];
    const float* d      = (const float*)d_in[3];
    const float* t1_w   = (const float*)d_in[4];
    const float* t1_b   = (const float*)d_in[5];
    const float* gate_w = (const float*)d_in[6];
    const float* gate_b = (const float*)d_in[7];
    const float* t2_w   = (const float*)d_in[8];
    const float* t2_b   = (const float*)d_in[9];
    float* out = (float*)d_out;

    // transform 1 (tensor cores, split-bf16 fp32 emulation)
    wconv_kernel<<<(HIDDEN * IN_DIM + 255) / 256, 256>>>(t1_w);
    gemm1_mma_kernel<<<(N_NODES + 127) / 128, 256>>>(h, t1_b);

    // CSR by dst
    zero_counts_kernel<<<(N_NODES + 255) / 256, 256>>>();
    hist_kernel<<<(N_EDGES + 255) / 256, 256>>>(dst);
    scan_blocks_kernel<<<SCAN_NB, 1024>>>();
    scan_sums_kernel<<<1, 64>>>();
    add_offsets_kernel<<<(N_NODES + 255) / 256, 256>>>();
    scatter_kernel<<<(N_EDGES + 255) / 256, 256>>>(dst);

    const int node_warp_blocks = (N_NODES * 32 + 255) / 256;  // 6250
    const int edge_blocks = (N_EDGES + 255) / 256;

    // layer 0: g_h0 -> g_hA
    gate_proj_kernel<<<node_warp_blocks, 256>>>(0, gate_w, 0);
    edge_coef_kernel<<<edge_blocks, 256>>>(src, dst, d, gate_b, 0);
    agg_kernel<<<node_warp_blocks, 256>>>(0, 1, src);

    // layer 1: g_hA -> g_hB
    gate_proj_kernel<<<node_warp_blocks, 256>>>(1, gate_w, 1);
    edge_coef_kernel<<<edge_blocks, 256>>>(src, dst, d, gate_b, 1);
    agg_kernel<<<node_warp_blocks, 256>>>(1, 2, src);

    // output head + log_softmax
    out_kernel<<<592, 256>>>(2, t2_w, t2_b, out);
}